// round 7
// baseline (speedup 1.0000x reference)
#include <cuda_runtime.h>
#include <cstdint>

#define BB 128
#define TT 4096
#define KK 64
#define START 62
#define STOP 63
#define NEGV -10000.0f

// packed backpointers: low byte = bp[t][j], high byte = bp[t-1][bp[t][j]]
__device__ unsigned short g_bp[(size_t)BB * TT * KK];   // 64 MB

__device__ __forceinline__ float frcp(float x) {
    float r; asm("rcp.approx.f32 %0, %1;" : "=f"(r) : "f"(x)); return r;
}
__device__ __forceinline__ void barF() { asm volatile("bar.sync 1, 256;" ::: "memory"); }
__device__ __forceinline__ void barV() { asm volatile("bar.sync 2, 256;" ::: "memory"); }

__global__ __launch_bounds__(512, 1)
void crf_kernel(const float* __restrict__ feats,
                const int*   __restrict__ tags,
                const float* __restrict__ trans,
                float*       __restrict__ out)
{
    __shared__ __align__(16) float a_buf[2][KK];
    __shared__ __align__(16) float d_buf[2][KK];
    __shared__ unsigned char cs[2][KK];
    __shared__ float tStop[KK];
    __shared__ float gred[64];
    __shared__ __align__(16) unsigned short stage[2][128 * KK];   // 2 x 16 KB

    const int b   = blockIdx.x;
    const int tid = threadIdx.x;
    const float* bf = feats + (size_t)b * TT * KK;
    unsigned short* bpb = g_bp + (size_t)b * TT * KK;
    int p = 0;
    float logscale = 0.0f;

    if (tid < 256) {
        // ========== FORWARD GROUP: warps 0-7, 4 threads per state ==========
        const int j = tid >> 2;        // state 0..63
        const int q = tid & 3;         // quarter of prev-state range
        float E[16];
#pragma unroll
        for (int k = 0; k < 16; k++)
            E[k] = __expf(trans[j * KK + q * 16 + k]);

        if (tid < KK) tStop[tid] = trans[STOP * KK + tid];
        if (q == 0) a_buf[0][j] = (j == START) ? 1.0f : 0.0f;

        // feats queue depth 4, exp pipeline depth 2
        float fq0 = bf[0 * KK + j], fq1 = bf[1 * KK + j];
        float fq2 = bf[2 * KK + j], fq3 = bf[3 * KK + j];
        float ef0 = __expf(fq0), ef1 = __expf(fq1);
        barF();

        for (int t = 0; t < TT; t++) {
            float ld = (t + 4 < TT) ? bf[(size_t)(t + 4) * KK + j] : 0.0f;

            const float4* av = (const float4*)&a_buf[p][q * 16];
            float4 A0 = av[0], A1 = av[1], A2 = av[2], A3 = av[3];
            float a0f = A0.x;                 // q==0: this is a_prev[0]
            float rM  = frcp(a0f);

            float c0, c1, c2, c3;
            c0 = E[0]  * A0.x; c1 = E[1]  * A0.y; c2 = E[2]  * A0.z; c3 = E[3]  * A0.w;
            c0 = fmaf(E[4],  A1.x, c0); c1 = fmaf(E[5],  A1.y, c1);
            c2 = fmaf(E[6],  A1.z, c2); c3 = fmaf(E[7],  A1.w, c3);
            c0 = fmaf(E[8],  A2.x, c0); c1 = fmaf(E[9],  A2.y, c1);
            c2 = fmaf(E[10], A2.z, c2); c3 = fmaf(E[11], A2.w, c3);
            c0 = fmaf(E[12], A3.x, c0); c1 = fmaf(E[13], A3.y, c1);
            c2 = fmaf(E[14], A3.z, c2); c3 = fmaf(E[15], A3.w, c3);
            float dot = (c0 + c1) + (c2 + c3);
            dot += __shfl_xor_sync(0xffffffffu, dot, 1);
            dot += __shfl_xor_sync(0xffffffffu, dot, 2);

            if (q == 0) {
                float lin = ef0 * dot;
                a_buf[p ^ 1][j] = (t == 0) ? lin : lin * rM;
            }
            barF();

            // trailing (hidden under next step)
            if (tid == 0 && t > 0) logscale += __logf(a0f);
            ef0 = ef1; ef1 = __expf(fq2);
            fq0 = fq1; fq1 = fq2; fq2 = fq3; fq3 = ld;
            p ^= 1;
        }
    } else {
        // ========== VITERBI GROUP: warps 8-15, 4 threads per state ==========
        const int vt = tid - 256;
        const int j = vt >> 2;
        const int q = vt & 3;
        float T[16];
#pragma unroll
        for (int k = 0; k < 16; k++)
            T[k] = trans[j * KK + q * 16 + k];

        if (q == 0) d_buf[0][j] = (j == START) ? 0.0f : NEGV;

        float fq0 = bf[0 * KK + j], fq1 = bf[1 * KK + j];
        float fq2 = bf[2 * KK + j], fq3 = bf[3 * KK + j];
        barV();

        for (int t = 0; t < TT; t++) {
            float ld = (t + 4 < TT) ? bf[(size_t)(t + 4) * KK + j] : 0.0f;

            const float4* dv = (const float4*)&d_buf[p][q * 16];
            float4 D0 = dv[0], D1 = dv[1], D2 = dv[2], D3 = dv[3];
            float v[16];
            v[0]  = T[0]  + D0.x; v[1]  = T[1]  + D0.y; v[2]  = T[2]  + D0.z; v[3]  = T[3]  + D0.w;
            v[4]  = T[4]  + D1.x; v[5]  = T[5]  + D1.y; v[6]  = T[6]  + D1.z; v[7]  = T[7]  + D1.w;
            v[8]  = T[8]  + D2.x; v[9]  = T[9]  + D2.y; v[10] = T[10] + D2.z; v[11] = T[11] + D2.w;
            v[12] = T[12] + D3.x; v[13] = T[13] + D3.y; v[14] = T[14] + D3.z; v[15] = T[15] + D3.w;

            float m0 = fmaxf(v[0],  v[4]),  m1 = fmaxf(v[1],  v[5]);
            float m2 = fmaxf(v[2],  v[6]),  m3 = fmaxf(v[3],  v[7]);
            m0 = fmaxf(m0, fmaxf(v[8],  v[12]));
            m1 = fmaxf(m1, fmaxf(v[9],  v[13]));
            m2 = fmaxf(m2, fmaxf(v[10], v[14]));
            m3 = fmaxf(m3, fmaxf(v[11], v[15]));
            float Mh = fmaxf(fmaxf(m0, m1), fmaxf(m2, m3));
            float M  = fmaxf(Mh, __shfl_xor_sync(0xffffffffu, Mh, 1));
            M = fmaxf(M, __shfl_xor_sync(0xffffffffu, M, 2));

            if (q == 0) d_buf[p ^ 1][j] = M + fq0;
            barV();

            // trailing: argmax mask + composed backpointer (off the chain path)
            unsigned msk = 0;
#pragma unroll
            for (int k = 0; k < 16; k++)
                msk |= (v[k] == M) ? (1u << k) : 0u;
            int cand = msk ? (q * 16 + __ffs(msk) - 1) : 1000;
            cand = min(cand, __shfl_xor_sync(0xffffffffu, cand, 1));
            cand = min(cand, __shfl_xor_sync(0xffffffffu, cand, 2));
            if (q == 0) {
                int b2 = (t == 0) ? cand : (int)cs[(t - 1) & 1][cand];
                cs[t & 1][j] = (unsigned char)cand;
                bpb[(size_t)t * KK + j] = (unsigned short)(cand | (b2 << 8));
            }
            fq0 = fq1; fq1 = fq2; fq2 = fq3; fq3 = ld;
            p ^= 1;
        }
    }

    __syncthreads();   // final state: a_buf[0], d_buf[0]; F threads' p == 0

    if (tid < 64) {
        // ---- gold score + nll (warps 0-1) ----
        const int* btags = tags + (size_t)b * TT;
        float g = 0.0f;
        for (int t = tid; t < TT; t += 64) {
            int tag  = btags[t];
            int prev = t ? btags[t - 1] : START;
            g += trans[tag * KK + prev] + bf[(size_t)t * KK + tag];
        }
        gred[tid] = g;
        asm volatile("bar.sync 4, 64;" ::: "memory");
        if (tid == 0) {
            float gold = 0.0f;
            for (int i = 0; i < 64; i++) gold += gred[i];
            gold += tStop[btags[TT - 1]];
            float s = 0.0f;
            for (int i = 0; i < KK; i++) s += a_buf[0][i] * __expf(tStop[i]);
            out[b] = (logscale + __logf(s)) - gold;
        }
    } else if (tid < 128) {
        // ---- viterbi terminal + backtrack (warps 2-3) ----
        int cur = 0;
        float* po = out + 2 * BB + (size_t)b * TT;
        if (tid == 64) {
            float best = -3.0e38f; int bl = 0;
            for (int i = 0; i < KK; i++) {
                float v = d_buf[0][i] + tStop[i];
                if (v > best) { best = v; bl = i; }
            }
            out[BB + b] = best;
            cur = bl;
            po[TT - 1] = (float)cur;
        }
        // preload chunk 31 into stage[1]
        {
            const uint4* src = (const uint4*)(bpb + (size_t)31 * 128 * KK);
            uint4* dst = (uint4*)stage[1];
            for (int i = tid - 64; i < 1024; i += 64) dst[i] = src[i];
        }
        asm volatile("bar.sync 3, 64;" ::: "memory");
        for (int c = 31; c >= 0; c--) {
            if (tid != 64 && c > 0) {
                const uint4* src = (const uint4*)(bpb + (size_t)(c - 1) * 128 * KK);
                uint4* dst = (uint4*)stage[(c - 1) & 1];
                for (int i = tid - 65; i < 1024; i += 63) dst[i] = src[i];
            }
            if (tid == 64) {
                const unsigned short* st = stage[c & 1];
#pragma unroll 4
                for (int tt = 127; tt >= 1; tt -= 2) {
                    unsigned w = st[tt * KK + cur];
                    int lo = w & 255, hi = w >> 8;
                    int gt = c * 128 + tt;
                    po[gt - 1] = (float)lo;
                    if (gt > 1) po[gt - 2] = (float)hi;
                    cur = hi;
                }
            }
            asm volatile("bar.sync 3, 64;" ::: "memory");
        }
    }
}

extern "C" void kernel_launch(void* const* d_in, const int* in_sizes, int n_in,
                              void* d_out, int out_size)
{
    const float* feats = (const float*)d_in[0];
    const int*   tags  = (const int*)d_in[1];
    const float* trans = (const float*)d_in[2];
    float* out = (float*)d_out;
    crf_kernel<<<BB, 512>>>(feats, tags, trans, out);
}

// round 8
// speedup vs baseline: 1.1675x; 1.1675x over previous
#include <cuda_runtime.h>
#include <cstdint>

#define BB 128
#define TT 4096
#define KK 64
#define START 62
#define STOP 63
#define NEGV -10000.0f

// packed backpointers: low byte = bp[t][j], high byte = bp[t-1][bp[t][j]]
__device__ unsigned short g_bp[(size_t)BB * TT * KK];   // 64 MB

__device__ __forceinline__ float frcp(float x) {
    float r; asm("rcp.approx.f32 %0, %1;" : "=f"(r) : "f"(x)); return r;
}
__device__ __forceinline__ unsigned ld_acq(const unsigned* p) {
    unsigned v;
    asm volatile("ld.acquire.cta.u32 %0, [%1];" : "=r"(v) : "l"(p) : "memory");
    return v;
}
__device__ __forceinline__ void st_rel(unsigned* p, unsigned v) {
    asm volatile("st.release.cta.u32 [%0], %1;" :: "l"(p), "r"(v) : "memory");
}

__global__ __launch_bounds__(256, 1)
void crf_kernel(const float* __restrict__ feats,
                const int*   __restrict__ tags,
                const float* __restrict__ trans,
                float*       __restrict__ out)
{
    __shared__ __align__(16) float a_buf[2][KK];
    __shared__ __align__(16) float d_buf[2][KK];
    __shared__ unsigned char cs[2][KK];
    __shared__ __align__(16) unsigned flagF[4];
    __shared__ __align__(16) unsigned flagV[4];
    __shared__ float tStop[KK];
    __shared__ float gred[64];
    __shared__ __align__(16) unsigned short stage[2][128 * KK];   // 2 x 16 KB

    const int b    = blockIdx.x;
    const int tid  = threadIdx.x;
    const int lane = tid & 31;
    const float* bf = feats + (size_t)b * TT * KK;
    unsigned short* bpb = g_bp + (size_t)b * TT * KK;
    float logscale = 0.0f;

    if (tid < 4) { flagF[tid] = 0; flagV[tid] = 0; }
    if (tid < KK) tStop[tid] = trans[STOP * KK + tid];

    if (tid < 128) {
        // ================= FORWARD GROUP (warps 0-3), 2 threads/state =================
        const int j = tid >> 1;
        const int h = tid & 1;
        const int w = tid >> 5;
        float E[32];
#pragma unroll
        for (int i = 0; i < 32; i++) E[i] = __expf(trans[j * KK + h * 32 + i]);

        if (h == 0) a_buf[0][j] = (j == START) ? 1.0f : 0.0f;

        float fq0 = bf[0 * KK + j], fq1 = bf[1 * KK + j];
        float fq2 = bf[2 * KK + j], fq3 = bf[3 * KK + j];
        float ef0 = __expf(fq0), ef1 = __expf(fq1);
        __syncthreads();

        int p = 0;
        for (int t = 0; t < TT; t++) {
            float ld = (t + 4 < TT) ? bf[(size_t)(t + 4) * KK + j] : 0.0f;

            if (t > 0) {
                unsigned tt = (unsigned)t;
                for (;;) {
                    unsigned f0 = ld_acq(&flagF[0]), f1 = ld_acq(&flagF[1]);
                    unsigned f2 = ld_acq(&flagF[2]), f3 = ld_acq(&flagF[3]);
                    if (min(min(f0, f1), min(f2, f3)) >= tt) break;
                }
            }

            const float4* av = (const float4*)(&a_buf[p][h * 32]);
            float4 A0 = av[0], A1 = av[1], A2 = av[2], A3 = av[3];
            float4 A4 = av[4], A5 = av[5], A6 = av[6], A7 = av[7];
            float a0f = A0.x;                  // h==0: a_prev[0]
            float rM  = frcp(a0f);

            float c0, c1, c2, c3;
            c0 = E[0]  * A0.x; c1 = E[1]  * A0.y; c2 = E[2]  * A0.z; c3 = E[3]  * A0.w;
            c0 = fmaf(E[4],  A1.x, c0); c1 = fmaf(E[5],  A1.y, c1);
            c2 = fmaf(E[6],  A1.z, c2); c3 = fmaf(E[7],  A1.w, c3);
            c0 = fmaf(E[8],  A2.x, c0); c1 = fmaf(E[9],  A2.y, c1);
            c2 = fmaf(E[10], A2.z, c2); c3 = fmaf(E[11], A2.w, c3);
            c0 = fmaf(E[12], A3.x, c0); c1 = fmaf(E[13], A3.y, c1);
            c2 = fmaf(E[14], A3.z, c2); c3 = fmaf(E[15], A3.w, c3);
            c0 = fmaf(E[16], A4.x, c0); c1 = fmaf(E[17], A4.y, c1);
            c2 = fmaf(E[18], A4.z, c2); c3 = fmaf(E[19], A4.w, c3);
            c0 = fmaf(E[20], A5.x, c0); c1 = fmaf(E[21], A5.y, c1);
            c2 = fmaf(E[22], A5.z, c2); c3 = fmaf(E[23], A5.w, c3);
            c0 = fmaf(E[24], A6.x, c0); c1 = fmaf(E[25], A6.y, c1);
            c2 = fmaf(E[26], A6.z, c2); c3 = fmaf(E[27], A6.w, c3);
            c0 = fmaf(E[28], A7.x, c0); c1 = fmaf(E[29], A7.y, c1);
            c2 = fmaf(E[30], A7.z, c2); c3 = fmaf(E[31], A7.w, c3);
            float dot = (c0 + c1) + (c2 + c3);
            dot += __shfl_xor_sync(0xffffffffu, dot, 1);

            if (h == 0) {
                float lin = ef0 * dot;
                a_buf[p ^ 1][j] = (t == 0) ? lin : lin * rM;
            }
            __syncwarp();
            if (lane == 0) st_rel(&flagF[w], (unsigned)(t + 1));

            // trailing (hidden under next step's spin of other warps)
            if (tid == 0 && t > 0) logscale += __logf(a0f);
            ef0 = ef1; ef1 = __expf(fq2);
            fq0 = fq1; fq1 = fq2; fq2 = fq3; fq3 = ld;
            p ^= 1;
        }
    } else {
        // ================= VITERBI GROUP (warps 4-7), 2 threads/state =================
        const int vt = tid - 128;
        const int j = vt >> 1;
        const int h = vt & 1;
        const int w = vt >> 5;
        float T[32];
#pragma unroll
        for (int i = 0; i < 32; i++) T[i] = trans[j * KK + h * 32 + i];

        if (h == 0) d_buf[0][j] = (j == START) ? 0.0f : NEGV;

        float fq0 = bf[0 * KK + j], fq1 = bf[1 * KK + j];
        float fq2 = bf[2 * KK + j], fq3 = bf[3 * KK + j];
        __syncthreads();

        int p = 0;
        for (int t = 0; t < TT; t++) {
            float ld = (t + 4 < TT) ? bf[(size_t)(t + 4) * KK + j] : 0.0f;

            if (t > 0) {
                unsigned tt = (unsigned)t;
                for (;;) {
                    unsigned f0 = ld_acq(&flagV[0]), f1 = ld_acq(&flagV[1]);
                    unsigned f2 = ld_acq(&flagV[2]), f3 = ld_acq(&flagV[3]);
                    if (min(min(f0, f1), min(f2, f3)) >= tt) break;
                }
            }

            const float4* dv = (const float4*)(&d_buf[p][h * 32]);
            float v[32];
            {
                float4 D0 = dv[0], D1 = dv[1], D2 = dv[2], D3 = dv[3];
                float4 D4 = dv[4], D5 = dv[5], D6 = dv[6], D7 = dv[7];
                v[0]  = T[0]  + D0.x; v[1]  = T[1]  + D0.y; v[2]  = T[2]  + D0.z; v[3]  = T[3]  + D0.w;
                v[4]  = T[4]  + D1.x; v[5]  = T[5]  + D1.y; v[6]  = T[6]  + D1.z; v[7]  = T[7]  + D1.w;
                v[8]  = T[8]  + D2.x; v[9]  = T[9]  + D2.y; v[10] = T[10] + D2.z; v[11] = T[11] + D2.w;
                v[12] = T[12] + D3.x; v[13] = T[13] + D3.y; v[14] = T[14] + D3.z; v[15] = T[15] + D3.w;
                v[16] = T[16] + D4.x; v[17] = T[17] + D4.y; v[18] = T[18] + D4.z; v[19] = T[19] + D4.w;
                v[20] = T[20] + D5.x; v[21] = T[21] + D5.y; v[22] = T[22] + D5.z; v[23] = T[23] + D5.w;
                v[24] = T[24] + D6.x; v[25] = T[25] + D6.y; v[26] = T[26] + D6.z; v[27] = T[27] + D6.w;
                v[28] = T[28] + D7.x; v[29] = T[29] + D7.y; v[30] = T[30] + D7.z; v[31] = T[31] + D7.w;
            }

            float m0 = fmaxf(v[0], v[4]),  m1 = fmaxf(v[1], v[5]);
            float m2 = fmaxf(v[2], v[6]),  m3 = fmaxf(v[3], v[7]);
            m0 = fmaxf(m0, fmaxf(v[8],  v[12]));
            m1 = fmaxf(m1, fmaxf(v[9],  v[13]));
            m2 = fmaxf(m2, fmaxf(v[10], v[14]));
            m3 = fmaxf(m3, fmaxf(v[11], v[15]));
            m0 = fmaxf(m0, fmaxf(v[16], v[20]));
            m1 = fmaxf(m1, fmaxf(v[17], v[21]));
            m2 = fmaxf(m2, fmaxf(v[18], v[22]));
            m3 = fmaxf(m3, fmaxf(v[19], v[23]));
            m0 = fmaxf(m0, fmaxf(v[24], v[28]));
            m1 = fmaxf(m1, fmaxf(v[25], v[29]));
            m2 = fmaxf(m2, fmaxf(v[26], v[30]));
            m3 = fmaxf(m3, fmaxf(v[27], v[31]));
            float Mh = fmaxf(fmaxf(m0, m1), fmaxf(m2, m3));
            float M  = fmaxf(Mh, __shfl_xor_sync(0xffffffffu, Mh, 1));

            // argmax mask (must precede flag: cs is read cross-state next step)
            unsigned msk0 = 0, msk1 = 0, msk2 = 0, msk3 = 0;
#pragma unroll
            for (int k = 0; k < 8; k++) {
                msk0 |= (v[4 * k + 0] == M) ? (1u << (4 * k + 0)) : 0u;
                msk1 |= (v[4 * k + 1] == M) ? (1u << (4 * k + 1)) : 0u;
                msk2 |= (v[4 * k + 2] == M) ? (1u << (4 * k + 2)) : 0u;
                msk3 |= (v[4 * k + 3] == M) ? (1u << (4 * k + 3)) : 0u;
            }
            unsigned msk = (msk0 | msk1) | (msk2 | msk3);
            int cand = msk ? (h * 32 + __ffs(msk) - 1) : 1000;
            cand = min(cand, __shfl_xor_sync(0xffffffffu, cand, 1));

            int b2 = 0;
            if (h == 0) {
                d_buf[p ^ 1][j] = M + fq0;
                b2 = (t == 0) ? cand : (int)cs[(t - 1) & 1][cand];
                cs[t & 1][j] = (unsigned char)cand;
            }
            __syncwarp();
            if (lane == 0) st_rel(&flagV[w], (unsigned)(t + 1));

            // trailing: global backpointer store (nobody reads until after the loop)
            if (h == 0)
                bpb[(size_t)t * KK + j] = (unsigned short)(cand | (b2 << 8));
            fq0 = fq1; fq1 = fq2; fq2 = fq3; fq3 = ld;
            p ^= 1;
        }
    }

    __syncthreads();   // final state: a_buf[0], d_buf[0]

    if (tid < 64) {
        // ---- gold score + nll (warps 0-1) ----
        const int* btags = tags + (size_t)b * TT;
        float g = 0.0f;
        for (int t = tid; t < TT; t += 64) {
            int tag  = btags[t];
            int prev = t ? btags[t - 1] : START;
            g += trans[tag * KK + prev] + bf[(size_t)t * KK + tag];
        }
        gred[tid] = g;
        asm volatile("bar.sync 4, 64;" ::: "memory");
        if (tid == 0) {
            float gold = 0.0f;
            for (int i = 0; i < 64; i++) gold += gred[i];
            gold += tStop[btags[TT - 1]];
            float s = 0.0f;
            for (int i = 0; i < KK; i++) s += a_buf[0][i] * __expf(tStop[i]);
            out[b] = (logscale + __logf(s)) - gold;
        }
    } else if (tid < 128) {
        // ---- viterbi terminal + backtrack (warps 2-3) ----
        int cur = 0;
        float* po = out + 2 * BB + (size_t)b * TT;
        if (tid == 64) {
            float best = -3.0e38f; int bl = 0;
            for (int i = 0; i < KK; i++) {
                float v = d_buf[0][i] + tStop[i];
                if (v > best) { best = v; bl = i; }
            }
            out[BB + b] = best;
            cur = bl;
            po[TT - 1] = (float)cur;
        }
        // preload chunk 31 into stage[1]
        {
            const uint4* src = (const uint4*)(bpb + (size_t)31 * 128 * KK);
            uint4* dst = (uint4*)stage[1];
            for (int i = tid - 64; i < 1024; i += 64) dst[i] = src[i];
        }
        asm volatile("bar.sync 3, 64;" ::: "memory");
        for (int c = 31; c >= 0; c--) {
            if (tid != 64 && c > 0) {
                const uint4* src = (const uint4*)(bpb + (size_t)(c - 1) * 128 * KK);
                uint4* dst = (uint4*)stage[(c - 1) & 1];
                for (int i = tid - 65; i < 1024; i += 63) dst[i] = src[i];
            }
            if (tid == 64) {
                const unsigned short* st = stage[c & 1];
#pragma unroll 4
                for (int tt = 127; tt >= 1; tt -= 2) {
                    unsigned w = st[tt * KK + cur];
                    int lo = w & 255, hi = w >> 8;
                    int gt = c * 128 + tt;
                    po[gt - 1] = (float)lo;
                    if (gt > 1) po[gt - 2] = (float)hi;
                    cur = hi;
                }
            }
            asm volatile("bar.sync 3, 64;" ::: "memory");
        }
    }
}

extern "C" void kernel_launch(void* const* d_in, const int* in_sizes, int n_in,
                              void* d_out, int out_size)
{
    const float* feats = (const float*)d_in[0];
    const int*   tags  = (const int*)d_in[1];
    const float* trans = (const float*)d_in[2];
    float* out = (float*)d_out;
    crf_kernel<<<BB, 256>>>(feats, tags, trans, out);
}

// round 10
// speedup vs baseline: 1.3276x; 1.1371x over previous
#include <cuda_runtime.h>
#include <cstdint>

#define BB 128
#define TT 4096
#define KK 64
#define START 62
#define STOP 63
#define NEGV -10000.0f
#define RING 16

// plain backpointers, u8
__device__ unsigned char g_bp[(size_t)BB * TT * KK];   // 32 MB

__device__ __forceinline__ float frcp(float x) {
    float r; asm("rcp.approx.f32 %0, %1;" : "=f"(r) : "f"(x)); return r;
}
__device__ __forceinline__ unsigned ld_acq(const unsigned* p) {
    unsigned v;
    asm volatile("ld.acquire.cta.shared.u32 %0, [%1];"
                 : "=r"(v) : "l"(__cvta_generic_to_shared(p)) : "memory");
    return v;
}
__device__ __forceinline__ void st_rel(unsigned* p, unsigned v) {
    asm volatile("st.release.cta.shared.u32 [%0], %1;"
                 :: "l"(__cvta_generic_to_shared(p)), "r"(v) : "memory");
}
__device__ __forceinline__ void barF() { asm volatile("bar.sync 1, 128;" ::: "memory"); }
__device__ __forceinline__ void barV() { asm volatile("bar.sync 2, 128;" ::: "memory"); }

__global__ __launch_bounds__(384, 1)
void crf_kernel(const float* __restrict__ feats,
                const int*   __restrict__ tags,
                const float* __restrict__ trans,
                float*       __restrict__ out)
{
    __shared__ __align__(16) float a_buf[2][KK];
    __shared__ __align__(16) float dring[RING][KK];   // dring[t&15] holds delta_t
    __shared__ unsigned Vcnt;                          // delta_0..delta_{Vcnt-1} valid
    __shared__ unsigned bpcnt[4];                      // per-bp-warp: steps completed
    __shared__ float tStop[KK];
    __shared__ float gred[64];
    __shared__ __align__(16) unsigned char stage[2][128 * KK];   // 2 x 8 KB

    const int b    = blockIdx.x;
    const int tid  = threadIdx.x;
    const float* bf = feats + (size_t)b * TT * KK;
    unsigned char* bpb = g_bp + (size_t)b * TT * KK;
    float logscale = 0.0f;

    if (tid == 0) Vcnt = 1;
    if (tid < 4) bpcnt[tid] = 0;
    if (tid < KK) {
        tStop[tid] = trans[STOP * KK + tid];
        a_buf[0][tid]  = (tid == START) ? 1.0f : 0.0f;
        dring[0][tid]  = (tid == START) ? 0.0f : NEGV;
    }

    if (tid < 128) {
        // ============ FORWARD warps 0-3: 2 lanes/state, bar 1 ============
        const int j = tid >> 1;
        const int h = tid & 1;
        float E[32];
#pragma unroll
        for (int i = 0; i < 32; i++) E[i] = __expf(trans[j * KK + h * 32 + i]);

        float fq0 = bf[0 * KK + j], fq1 = bf[1 * KK + j];
        float fq2 = bf[2 * KK + j], fq3 = bf[3 * KK + j];
        float ef0 = __expf(fq0), ef1 = __expf(fq1);
        __syncthreads();

        int p = 0;
        for (int t = 0; t < TT; t++) {
            float ld = (t + 4 < TT) ? bf[(size_t)(t + 4) * KK + j] : 0.0f;

            const float4* av = (const float4*)(&a_buf[p][h * 32]);
            float4 A0 = av[0], A1 = av[1], A2 = av[2], A3 = av[3];
            float4 A4 = av[4], A5 = av[5], A6 = av[6], A7 = av[7];
            float a0f = A0.x;                  // h==0: a_prev[0]
            float rM  = frcp(a0f);

            float c0, c1, c2, c3;
            c0 = E[0]  * A0.x; c1 = E[1]  * A0.y; c2 = E[2]  * A0.z; c3 = E[3]  * A0.w;
            c0 = fmaf(E[4],  A1.x, c0); c1 = fmaf(E[5],  A1.y, c1);
            c2 = fmaf(E[6],  A1.z, c2); c3 = fmaf(E[7],  A1.w, c3);
            c0 = fmaf(E[8],  A2.x, c0); c1 = fmaf(E[9],  A2.y, c1);
            c2 = fmaf(E[10], A2.z, c2); c3 = fmaf(E[11], A2.w, c3);
            c0 = fmaf(E[12], A3.x, c0); c1 = fmaf(E[13], A3.y, c1);
            c2 = fmaf(E[14], A3.z, c2); c3 = fmaf(E[15], A3.w, c3);
            c0 = fmaf(E[16], A4.x, c0); c1 = fmaf(E[17], A4.y, c1);
            c2 = fmaf(E[18], A4.z, c2); c3 = fmaf(E[19], A4.w, c3);
            c0 = fmaf(E[20], A5.x, c0); c1 = fmaf(E[21], A5.y, c1);
            c2 = fmaf(E[22], A5.z, c2); c3 = fmaf(E[23], A5.w, c3);
            c0 = fmaf(E[24], A6.x, c0); c1 = fmaf(E[25], A6.y, c1);
            c2 = fmaf(E[26], A6.z, c2); c3 = fmaf(E[27], A6.w, c3);
            c0 = fmaf(E[28], A7.x, c0); c1 = fmaf(E[29], A7.y, c1);
            c2 = fmaf(E[30], A7.z, c2); c3 = fmaf(E[31], A7.w, c3);
            float dot = (c0 + c1) + (c2 + c3);
            dot += __shfl_xor_sync(0xffffffffu, dot, 1);

            if (h == 0) {
                float lin = ef0 * dot;
                a_buf[p ^ 1][j] = (t == 0) ? lin : lin * rM;
            }
            barF();
            if (tid == 0 && t > 0) logscale += __logf(a0f);
            ef0 = ef1; ef1 = __expf(fq2);
            fq0 = fq1; fq1 = fq2; fq2 = fq3; fq3 = ld;
            p ^= 1;
        }
    } else if (tid < 256) {
        // ============ VITERBI warps 4-7 (lean max-plus), 2 lanes/state, bar 2 ============
        const int vt = tid - 128;
        const int j = vt >> 1;
        const int h = vt & 1;
        float T[32];
#pragma unroll
        for (int i = 0; i < 32; i++) T[i] = trans[j * KK + h * 32 + i];

        float fq0 = bf[0 * KK + j], fq1 = bf[1 * KK + j];
        float fq2 = bf[2 * KK + j], fq3 = bf[3 * KK + j];
        __syncthreads();

        for (int t = 0; t < TT; t++) {
            float ld = (t + 4 < TT) ? bf[(size_t)(t + 4) * KK + j] : 0.0f;

            // backpressure: writing slot (t+1)&15 clobbers delta_{t-15}; before
            // each 8-step burst make sure bp warps consumed delta_{t-8}..
            if (t >= 16 && (t & 7) == 0) {
                unsigned need = (unsigned)(t - 7);
                for (;;) {
                    unsigned b0 = ld_acq(&bpcnt[0]), b1 = ld_acq(&bpcnt[1]);
                    unsigned b2 = ld_acq(&bpcnt[2]), b3 = ld_acq(&bpcnt[3]);
                    if (min(min(b0, b1), min(b2, b3)) >= need) break;
                    __nanosleep(40);
                }
            }

            const float4* dv = (const float4*)(&dring[t & (RING - 1)][h * 32]);
            float4 D0 = dv[0], D1 = dv[1], D2 = dv[2], D3 = dv[3];
            float4 D4 = dv[4], D5 = dv[5], D6 = dv[6], D7 = dv[7];
            float m0, m1, m2, m3;
            m0 = T[0]  + D0.x; m1 = T[1]  + D0.y; m2 = T[2]  + D0.z; m3 = T[3]  + D0.w;
            m0 = fmaxf(m0, T[4]  + D1.x); m1 = fmaxf(m1, T[5]  + D1.y);
            m2 = fmaxf(m2, T[6]  + D1.z); m3 = fmaxf(m3, T[7]  + D1.w);
            m0 = fmaxf(m0, T[8]  + D2.x); m1 = fmaxf(m1, T[9]  + D2.y);
            m2 = fmaxf(m2, T[10] + D2.z); m3 = fmaxf(m3, T[11] + D2.w);
            m0 = fmaxf(m0, T[12] + D3.x); m1 = fmaxf(m1, T[13] + D3.y);
            m2 = fmaxf(m2, T[14] + D3.z); m3 = fmaxf(m3, T[15] + D3.w);
            m0 = fmaxf(m0, T[16] + D4.x); m1 = fmaxf(m1, T[17] + D4.y);
            m2 = fmaxf(m2, T[18] + D4.z); m3 = fmaxf(m3, T[19] + D4.w);
            m0 = fmaxf(m0, T[20] + D5.x); m1 = fmaxf(m1, T[21] + D5.y);
            m2 = fmaxf(m2, T[22] + D5.z); m3 = fmaxf(m3, T[23] + D5.w);
            m0 = fmaxf(m0, T[24] + D6.x); m1 = fmaxf(m1, T[25] + D6.y);
            m2 = fmaxf(m2, T[26] + D6.z); m3 = fmaxf(m3, T[27] + D6.w);
            m0 = fmaxf(m0, T[28] + D7.x); m1 = fmaxf(m1, T[29] + D7.y);
            m2 = fmaxf(m2, T[30] + D7.z); m3 = fmaxf(m3, T[31] + D7.w);
            float Mh = fmaxf(fmaxf(m0, m1), fmaxf(m2, m3));
            float M  = fmaxf(Mh, __shfl_xor_sync(0xffffffffu, Mh, 1));

            if (h == 0) dring[(t + 1) & (RING - 1)][j] = M + fq0;
            barV();
            if (vt == 0) st_rel(&Vcnt, (unsigned)(t + 2));

            fq0 = fq1; fq1 = fq2; fq2 = fq3; fq3 = ld;
        }
    } else {
        // ============ BP warps 8-11: async argmax recompute, no barriers ============
        const int bl = tid - 256;         // 0..127
        const int w  = bl >> 5;           // bp warp id 0..3
        const int lane = bl & 31;
        const int j = w * 16 + (lane >> 1);
        const int h = lane & 1;
        float T[32];
#pragma unroll
        for (int i = 0; i < 32; i++) T[i] = trans[j * KK + h * 32 + i];
        __syncthreads();

        for (int tau = 0; tau < TT; tau++) {
            // need delta_tau valid: Vcnt >= tau+1
            unsigned need = (unsigned)(tau + 1);
            while (ld_acq(&Vcnt) < need) { __nanosleep(20); }

            const float4* dv = (const float4*)(&dring[tau & (RING - 1)][h * 32]);
            float4 D0 = dv[0], D1 = dv[1], D2 = dv[2], D3 = dv[3];
            float4 D4 = dv[4], D5 = dv[5], D6 = dv[6], D7 = dv[7];
            float v[32];
            v[0]  = T[0]  + D0.x; v[1]  = T[1]  + D0.y; v[2]  = T[2]  + D0.z; v[3]  = T[3]  + D0.w;
            v[4]  = T[4]  + D1.x; v[5]  = T[5]  + D1.y; v[6]  = T[6]  + D1.z; v[7]  = T[7]  + D1.w;
            v[8]  = T[8]  + D2.x; v[9]  = T[9]  + D2.y; v[10] = T[10] + D2.z; v[11] = T[11] + D2.w;
            v[12] = T[12] + D3.x; v[13] = T[13] + D3.y; v[14] = T[14] + D3.z; v[15] = T[15] + D3.w;
            v[16] = T[16] + D4.x; v[17] = T[17] + D4.y; v[18] = T[18] + D4.z; v[19] = T[19] + D4.w;
            v[20] = T[20] + D5.x; v[21] = T[21] + D5.y; v[22] = T[22] + D5.z; v[23] = T[23] + D5.w;
            v[24] = T[24] + D6.x; v[25] = T[25] + D6.y; v[26] = T[26] + D6.z; v[27] = T[27] + D6.w;
            v[28] = T[28] + D7.x; v[29] = T[29] + D7.y; v[30] = T[30] + D7.z; v[31] = T[31] + D7.w;

            float m0 = fmaxf(v[0], v[4]),  m1 = fmaxf(v[1], v[5]);
            float m2 = fmaxf(v[2], v[6]),  m3 = fmaxf(v[3], v[7]);
            m0 = fmaxf(m0, fmaxf(v[8],  v[12]));
            m1 = fmaxf(m1, fmaxf(v[9],  v[13]));
            m2 = fmaxf(m2, fmaxf(v[10], v[14]));
            m3 = fmaxf(m3, fmaxf(v[11], v[15]));
            m0 = fmaxf(m0, fmaxf(v[16], v[20]));
            m1 = fmaxf(m1, fmaxf(v[17], v[21]));
            m2 = fmaxf(m2, fmaxf(v[18], v[22]));
            m3 = fmaxf(m3, fmaxf(v[19], v[23]));
            m0 = fmaxf(m0, fmaxf(v[24], v[28]));
            m1 = fmaxf(m1, fmaxf(v[25], v[29]));
            m2 = fmaxf(m2, fmaxf(v[26], v[30]));
            m3 = fmaxf(m3, fmaxf(v[27], v[31]));
            float Mh = fmaxf(fmaxf(m0, m1), fmaxf(m2, m3));
            float M  = fmaxf(Mh, __shfl_xor_sync(0xffffffffu, Mh, 1));

            unsigned msk0 = 0, msk1 = 0, msk2 = 0, msk3 = 0;
#pragma unroll
            for (int k = 0; k < 8; k++) {
                msk0 |= (v[4 * k + 0] == M) ? (1u << (4 * k + 0)) : 0u;
                msk1 |= (v[4 * k + 1] == M) ? (1u << (4 * k + 1)) : 0u;
                msk2 |= (v[4 * k + 2] == M) ? (1u << (4 * k + 2)) : 0u;
                msk3 |= (v[4 * k + 3] == M) ? (1u << (4 * k + 3)) : 0u;
            }
            unsigned msk = (msk0 | msk1) | (msk2 | msk3);
            int cand = msk ? (h * 32 + __ffs(msk) - 1) : 1000;
            cand = min(cand, __shfl_xor_sync(0xffffffffu, cand, 1));
            if (h == 0) bpb[(size_t)tau * KK + j] = (unsigned char)cand;

            __syncwarp();
            if (lane == 0) st_rel(&bpcnt[w], (unsigned)(tau + 1));
        }
    }

    __syncthreads();   // final: a_buf[0] holds a_TT, dring[0] holds delta_TT (4096%16==0)

    if (tid < 64) {
        // ---- gold score + nll ----
        const int* btags = tags + (size_t)b * TT;
        float g = 0.0f;
        for (int t = tid; t < TT; t += 64) {
            int tag  = btags[t];
            int prev = t ? btags[t - 1] : START;
            g += trans[tag * KK + prev] + bf[(size_t)t * KK + tag];
        }
        gred[tid] = g;
        asm volatile("bar.sync 4, 64;" ::: "memory");
        if (tid == 0) {
            float gold = 0.0f;
            for (int i = 0; i < 64; i++) gold += gred[i];
            gold += tStop[btags[TT - 1]];
            float s = 0.0f;
            for (int i = 0; i < KK; i++) s += a_buf[0][i] * __expf(tStop[i]);
            out[b] = (logscale + __logf(s)) - gold;
        }
    } else if (tid < 128) {
        // ---- viterbi terminal + backtrack ----
        int cur = 0;
        float* po = out + 2 * BB + (size_t)b * TT;
        if (tid == 64) {
            float best = -3.0e38f; int bl2 = 0;
            for (int i = 0; i < KK; i++) {
                float v = dring[0][i] + tStop[i];
                if (v > best) { best = v; bl2 = i; }
            }
            out[BB + b] = best;
            cur = bl2;
            po[TT - 1] = (float)cur;
        }
        // backtrack: path[t-1] = bp[t][path[t]], staged in 128-step chunks
        {
            const uint4* src = (const uint4*)(bpb + (size_t)31 * 128 * KK);
            uint4* dst = (uint4*)stage[1];
            for (int i = tid - 64; i < 512; i += 64) dst[i] = src[i];
        }
        asm volatile("bar.sync 3, 64;" ::: "memory");
        for (int c = 31; c >= 0; c--) {
            if (tid != 64 && c > 0) {
                const uint4* src = (const uint4*)(bpb + (size_t)(c - 1) * 128 * KK);
                uint4* dst = (uint4*)stage[(c - 1) & 1];
                for (int i = tid - 65; i < 512; i += 63) dst[i] = src[i];
            }
            if (tid == 64) {
                const unsigned char* st = stage[c & 1];
                int tlo = (c == 0) ? 1 : 0;
#pragma unroll 4
                for (int tt = 127; tt >= tlo; tt--) {
                    cur = st[tt * KK + cur];
                    int gt = c * 128 + tt;
                    po[gt - 1] = (float)cur;
                }
            }
            asm volatile("bar.sync 3, 64;" ::: "memory");
        }
    }
}

extern "C" void kernel_launch(void* const* d_in, const int* in_sizes, int n_in,
                              void* d_out, int out_size)
{
    const float* feats = (const float*)d_in[0];
    const int*   tags  = (const int*)d_in[1];
    const float* trans = (const float*)d_in[2];
    float* out = (float*)d_out;
    crf_kernel<<<BB, 384>>>(feats, tags, trans, out);
}

// round 13
// speedup vs baseline: 1.3940x; 1.0500x over previous
#include <cuda_runtime.h>
#include <cstdint>

#define BB 128
#define TT 4096
#define KK 64
#define START 62
#define STOP 63
#define NEGV -10000.0f
#define RING 64

// plain backpointers, u8
__device__ unsigned char g_bp[(size_t)BB * TT * KK];   // 32 MB

__device__ __forceinline__ float frcp(float x) {
    float r; asm("rcp.approx.f32 %0, %1;" : "=f"(r) : "f"(x)); return r;
}
__device__ __forceinline__ unsigned ld_acq(const unsigned* p) {
    unsigned v;
    asm volatile("ld.acquire.cta.shared.u32 %0, [%1];"
                 : "=r"(v) : "l"(__cvta_generic_to_shared(p)) : "memory");
    return v;
}
__device__ __forceinline__ void st_rel(unsigned* p, unsigned v) {
    asm volatile("st.release.cta.shared.u32 [%0], %1;"
                 :: "l"(__cvta_generic_to_shared(p)), "r"(v) : "memory");
}
__device__ __forceinline__ void barF() { asm volatile("bar.sync 1, 128;" ::: "memory"); }
__device__ __forceinline__ void barV() { asm volatile("bar.sync 2, 128;" ::: "memory"); }

__global__ __launch_bounds__(384, 1)
void crf_kernel(const float* __restrict__ feats,
                const int*   __restrict__ tags,
                const float* __restrict__ trans,
                float*       __restrict__ out)
{
    __shared__ __align__(16) float a_buf[2][KK];
    __shared__ __align__(16) float dring[RING][KK];   // dring[t&63] = delta_t
    __shared__ __align__(16) float mring[RING][KK];   // mring[t&63] = M_t (pre-emission max)
    __shared__ unsigned Vcnt;                          // M_0..M_{Vcnt-1} and delta_0..delta_{Vcnt} valid
    __shared__ unsigned bpcnt[4];                      // per-bp-warp: taus completed
    __shared__ float tStop[KK];
    __shared__ float gred[64];
    __shared__ __align__(16) unsigned char stage[2][64 * KK];    // 2 x 4 KB

    const int b    = blockIdx.x;
    const int tid  = threadIdx.x;
    const float* bf = feats + (size_t)b * TT * KK;
    unsigned char* bpb = g_bp + (size_t)b * TT * KK;
    float logscale = 0.0f;

    if (tid == 0) Vcnt = 0;
    if (tid < 4) bpcnt[tid] = 0;
    if (tid < KK) {
        tStop[tid] = trans[STOP * KK + tid];
        a_buf[0][tid] = (tid == START) ? 1.0f : 0.0f;
        dring[0][tid] = (tid == START) ? 0.0f : NEGV;
    }

    if (tid < 128) {
        // ============ FORWARD warps 0-3: 2 lanes/state, bar 1 ============
        const int j = tid >> 1;
        const int h = tid & 1;
        float E[32];
#pragma unroll
        for (int i = 0; i < 32; i++) E[i] = __expf(trans[j * KK + h * 32 + i]);

        float fq0 = bf[0 * KK + j], fq1 = bf[1 * KK + j];
        float fq2 = bf[2 * KK + j], fq3 = bf[3 * KK + j];
        float ef0 = __expf(fq0), ef1 = __expf(fq1);
        __syncthreads();

        int p = 0;
        for (int t = 0; t < TT; t++) {
            float ld = (t + 4 < TT) ? bf[(size_t)(t + 4) * KK + j] : 0.0f;

            const float4* av = (const float4*)(&a_buf[p][h * 32]);
            float4 A0 = av[0], A1 = av[1], A2 = av[2], A3 = av[3];
            float4 A4 = av[4], A5 = av[5], A6 = av[6], A7 = av[7];
            float a0f = A0.x;                  // h==0: a_prev[0]
            float rM  = frcp(a0f);

            float c0, c1, c2, c3;
            c0 = E[0]  * A0.x; c1 = E[1]  * A0.y; c2 = E[2]  * A0.z; c3 = E[3]  * A0.w;
            c0 = fmaf(E[4],  A1.x, c0); c1 = fmaf(E[5],  A1.y, c1);
            c2 = fmaf(E[6],  A1.z, c2); c3 = fmaf(E[7],  A1.w, c3);
            c0 = fmaf(E[8],  A2.x, c0); c1 = fmaf(E[9],  A2.y, c1);
            c2 = fmaf(E[10], A2.z, c2); c3 = fmaf(E[11], A2.w, c3);
            c0 = fmaf(E[12], A3.x, c0); c1 = fmaf(E[13], A3.y, c1);
            c2 = fmaf(E[14], A3.z, c2); c3 = fmaf(E[15], A3.w, c3);
            c0 = fmaf(E[16], A4.x, c0); c1 = fmaf(E[17], A4.y, c1);
            c2 = fmaf(E[18], A4.z, c2); c3 = fmaf(E[19], A4.w, c3);
            c0 = fmaf(E[20], A5.x, c0); c1 = fmaf(E[21], A5.y, c1);
            c2 = fmaf(E[22], A5.z, c2); c3 = fmaf(E[23], A5.w, c3);
            c0 = fmaf(E[24], A6.x, c0); c1 = fmaf(E[25], A6.y, c1);
            c2 = fmaf(E[26], A6.z, c2); c3 = fmaf(E[27], A6.w, c3);
            c0 = fmaf(E[28], A7.x, c0); c1 = fmaf(E[29], A7.y, c1);
            c2 = fmaf(E[30], A7.z, c2); c3 = fmaf(E[31], A7.w, c3);
            float dot = (c0 + c1) + (c2 + c3);
            dot += __shfl_xor_sync(0xffffffffu, dot, 1);

            if (h == 0) {
                float lin = ef0 * dot;
                a_buf[p ^ 1][j] = (t == 0) ? lin : lin * rM;
            }
            barF();
            if (tid == 0 && t > 0) logscale += __logf(a0f);
            ef0 = ef1; ef1 = __expf(fq2);
            fq0 = fq1; fq1 = fq2; fq2 = fq3; fq3 = ld;
            p ^= 1;
        }
    } else if (tid < 256) {
        // ============ VITERBI warps 4-7 (lean), 2 lanes/state, bar 2 ============
        const int vt = tid - 128;
        const int j = vt >> 1;
        const int h = vt & 1;
        float T[32];
#pragma unroll
        for (int i = 0; i < 32; i++) T[i] = trans[j * KK + h * 32 + i];

        float fq0 = bf[0 * KK + j], fq1 = bf[1 * KK + j];
        float fq2 = bf[2 * KK + j], fq3 = bf[3 * KK + j];
        __syncthreads();

        for (int t = 0; t < TT; t++) {
            float ld = (t + 4 < TT) ? bf[(size_t)(t + 4) * KK + j] : 0.0f;

            // backpressure once per 16 steps: writing slot (t+1)&63 clobbers
            // delta_{t-63}; require BP done through tau = t-48.
            if (t >= 64 && (t & 15) == 0) {
                unsigned need = (unsigned)(t - 47);
                for (;;) {
                    unsigned b0 = ld_acq(&bpcnt[0]), b1 = ld_acq(&bpcnt[1]);
                    unsigned b2 = ld_acq(&bpcnt[2]), b3 = ld_acq(&bpcnt[3]);
                    if (min(min(b0, b1), min(b2, b3)) >= need) break;
                    __nanosleep(60);
                }
            }

            const float4* dv = (const float4*)(&dring[t & (RING - 1)][h * 32]);
            float4 D0 = dv[0], D1 = dv[1], D2 = dv[2], D3 = dv[3];
            float4 D4 = dv[4], D5 = dv[5], D6 = dv[6], D7 = dv[7];
            float m0, m1, m2, m3;
            m0 = T[0]  + D0.x; m1 = T[1]  + D0.y; m2 = T[2]  + D0.z; m3 = T[3]  + D0.w;
            m0 = fmaxf(m0, T[4]  + D1.x); m1 = fmaxf(m1, T[5]  + D1.y);
            m2 = fmaxf(m2, T[6]  + D1.z); m3 = fmaxf(m3, T[7]  + D1.w);
            m0 = fmaxf(m0, T[8]  + D2.x); m1 = fmaxf(m1, T[9]  + D2.y);
            m2 = fmaxf(m2, T[10] + D2.z); m3 = fmaxf(m3, T[11] + D2.w);
            m0 = fmaxf(m0, T[12] + D3.x); m1 = fmaxf(m1, T[13] + D3.y);
            m2 = fmaxf(m2, T[14] + D3.z); m3 = fmaxf(m3, T[15] + D3.w);
            m0 = fmaxf(m0, T[16] + D4.x); m1 = fmaxf(m1, T[17] + D4.y);
            m2 = fmaxf(m2, T[18] + D4.z); m3 = fmaxf(m3, T[19] + D4.w);
            m0 = fmaxf(m0, T[20] + D5.x); m1 = fmaxf(m1, T[21] + D5.y);
            m2 = fmaxf(m2, T[22] + D5.z); m3 = fmaxf(m3, T[23] + D5.w);
            m0 = fmaxf(m0, T[24] + D6.x); m1 = fmaxf(m1, T[25] + D6.y);
            m2 = fmaxf(m2, T[26] + D6.z); m3 = fmaxf(m3, T[27] + D6.w);
            m0 = fmaxf(m0, T[28] + D7.x); m1 = fmaxf(m1, T[29] + D7.y);
            m2 = fmaxf(m2, T[30] + D7.z); m3 = fmaxf(m3, T[31] + D7.w);
            float Mh = fmaxf(fmaxf(m0, m1), fmaxf(m2, m3));
            float M  = fmaxf(Mh, __shfl_xor_sync(0xffffffffu, Mh, 1));

            if (h == 0) {
                mring[t & (RING - 1)][j]       = M;
                dring[(t + 1) & (RING - 1)][j] = M + fq0;
            }
            barV();
            // publish progress once per 16 steps (after barV so all stores drained)
            if (vt == 0 && (t & 15) == 15) st_rel(&Vcnt, (unsigned)(t + 1));

            fq0 = fq1; fq1 = fq2; fq2 = fq3; fq3 = ld;
        }
    } else {
        // ============ BP warps 8-11: chunked argmax (no max tree — uses M ring) ============
        const int bl = tid - 256;
        const int w  = bl >> 5;
        const int lane = bl & 31;
        const int j = w * 16 + (lane >> 1);
        const int h = lane & 1;
        float T[32];
#pragma unroll
        for (int i = 0; i < 32; i++) T[i] = trans[j * KK + h * 32 + i];
        __syncthreads();

        for (int c = 0; c < TT / 16; c++) {
            unsigned need = (unsigned)(c * 16 + 16);    // M_0..M_{16c+15} valid
            while (ld_acq(&Vcnt) < need) { __nanosleep(60); }

#pragma unroll 2
            for (int tt = 0; tt < 16; tt++) {
                int tau = c * 16 + tt;
                const float4* dv = (const float4*)(&dring[tau & (RING - 1)][h * 32]);
                float4 D0 = dv[0], D1 = dv[1], D2 = dv[2], D3 = dv[3];
                float4 D4 = dv[4], D5 = dv[5], D6 = dv[6], D7 = dv[7];
                float M = mring[tau & (RING - 1)][j];

                unsigned msk0 = 0, msk1 = 0, msk2 = 0, msk3 = 0;
                msk0 |= (T[0]  + D0.x == M) ? (1u << 0)  : 0u;
                msk1 |= (T[1]  + D0.y == M) ? (1u << 1)  : 0u;
                msk2 |= (T[2]  + D0.z == M) ? (1u << 2)  : 0u;
                msk3 |= (T[3]  + D0.w == M) ? (1u << 3)  : 0u;
                msk0 |= (T[4]  + D1.x == M) ? (1u << 4)  : 0u;
                msk1 |= (T[5]  + D1.y == M) ? (1u << 5)  : 0u;
                msk2 |= (T[6]  + D1.z == M) ? (1u << 6)  : 0u;
                msk3 |= (T[7]  + D1.w == M) ? (1u << 7)  : 0u;
                msk0 |= (T[8]  + D2.x == M) ? (1u << 8)  : 0u;
                msk1 |= (T[9]  + D2.y == M) ? (1u << 9)  : 0u;
                msk2 |= (T[10] + D2.z == M) ? (1u << 10) : 0u;
                msk3 |= (T[11] + D2.w == M) ? (1u << 11) : 0u;
                msk0 |= (T[12] + D3.x == M) ? (1u << 12) : 0u;
                msk1 |= (T[13] + D3.y == M) ? (1u << 13) : 0u;
                msk2 |= (T[14] + D3.z == M) ? (1u << 14) : 0u;
                msk3 |= (T[15] + D3.w == M) ? (1u << 15) : 0u;
                msk0 |= (T[16] + D4.x == M) ? (1u << 16) : 0u;
                msk1 |= (T[17] + D4.y == M) ? (1u << 17) : 0u;
                msk2 |= (T[18] + D4.z == M) ? (1u << 18) : 0u;
                msk3 |= (T[19] + D4.w == M) ? (1u << 19) : 0u;
                msk0 |= (T[20] + D5.x == M) ? (1u << 20) : 0u;
                msk1 |= (T[21] + D5.y == M) ? (1u << 21) : 0u;
                msk2 |= (T[22] + D5.z == M) ? (1u << 22) : 0u;
                msk3 |= (T[23] + D5.w == M) ? (1u << 23) : 0u;
                msk0 |= (T[24] + D6.x == M) ? (1u << 24) : 0u;
                msk1 |= (T[25] + D6.y == M) ? (1u << 25) : 0u;
                msk2 |= (T[26] + D6.z == M) ? (1u << 26) : 0u;
                msk3 |= (T[27] + D6.w == M) ? (1u << 27) : 0u;
                msk0 |= (T[28] + D7.x == M) ? (1u << 28) : 0u;
                msk1 |= (T[29] + D7.y == M) ? (1u << 29) : 0u;
                msk2 |= (T[30] + D7.z == M) ? (1u << 30) : 0u;
                msk3 |= (T[31] + D7.w == M) ? (1u << 31) : 0u;
                unsigned msk = (msk0 | msk1) | (msk2 | msk3);
                int cand = msk ? (h * 32 + __ffs(msk) - 1) : 1000;
                cand = min(cand, __shfl_xor_sync(0xffffffffu, cand, 1));
                if (h == 0) bpb[(size_t)tau * KK + j] = (unsigned char)cand;
            }
            __syncwarp();
            if (lane == 0) st_rel(&bpcnt[w], (unsigned)(c * 16 + 16));
        }
    }

    __syncthreads();   // final: a_buf[0] = a_TT, dring[0] = delta_TT (4096%64==0)

    if (tid < 64) {
        // ---- gold score + nll ----
        const int* btags = tags + (size_t)b * TT;
        float g = 0.0f;
        for (int t = tid; t < TT; t += 64) {
            int tag  = btags[t];
            int prev = t ? btags[t - 1] : START;
            g += trans[tag * KK + prev] + bf[(size_t)t * KK + tag];
        }
        gred[tid] = g;
        asm volatile("bar.sync 4, 64;" ::: "memory");
        if (tid == 0) {
            float gold = 0.0f;
            for (int i = 0; i < 64; i++) gold += gred[i];
            gold += tStop[btags[TT - 1]];
            float s = 0.0f;
            for (int i = 0; i < KK; i++) s += a_buf[0][i] * __expf(tStop[i]);
            out[b] = (logscale + __logf(s)) - gold;
        }
    } else if (tid < 128) {
        // ---- viterbi terminal + backtrack ----
        int cur = 0;
        float* po = out + 2 * BB + (size_t)b * TT;
        if (tid == 64) {
            float best = -3.0e38f; int bl2 = 0;
            for (int i = 0; i < KK; i++) {
                float v = dring[0][i] + tStop[i];
                if (v > best) { best = v; bl2 = i; }
            }
            out[BB + b] = best;
            cur = bl2;
            po[TT - 1] = (float)cur;
        }
        // backtrack: path[t-1] = bp[t][path[t]], staged in 64-step chunks
        {
            const uint4* src = (const uint4*)(bpb + (size_t)63 * 64 * KK);
            uint4* dst = (uint4*)stage[1];
            for (int i = tid - 64; i < 256; i += 64) dst[i] = src[i];
        }
        asm volatile("bar.sync 3, 64;" ::: "memory");
        for (int c = 63; c >= 0; c--) {
            if (tid != 64 && c > 0) {
                const uint4* src = (const uint4*)(bpb + (size_t)(c - 1) * 64 * KK);
                uint4* dst = (uint4*)stage[(c - 1) & 1];
                for (int i = tid - 65; i < 256; i += 63) dst[i] = src[i];
            }
            if (tid == 64) {
                const unsigned char* st = stage[c & 1];
                int tlo = (c == 0) ? 1 : 0;
#pragma unroll 4
                for (int tt = 63; tt >= tlo; tt--) {
                    cur = st[tt * KK + cur];
                    int gt = c * 64 + tt;
                    po[gt - 1] = (float)cur;
                }
            }
            asm volatile("bar.sync 3, 64;" ::: "memory");
        }
    }
}

extern "C" void kernel_launch(void* const* d_in, const int* in_sizes, int n_in,
                              void* d_out, int out_size)
{
    const float* feats = (const float*)d_in[0];
    const int*   tags  = (const int*)d_in[1];
    const float* trans = (const float*)d_in[2];
    float* out = (float*)d_out;
    crf_kernel<<<BB, 384>>>(feats, tags, trans, out);
}